// round 1
// baseline (speedup 1.0000x reference)
#include <cuda_runtime.h>
#include <cuda_bf16.h>

// ColorReducer: out[b,:,h,w] = palette[argmin_k ||x[b,:,h,w] - palette[k]||^2]
// x: (B, 3, H, W) fp32 planar. palette: (NC, 3) fp32. Shapes per problem: B=8, H=W=512, NC=64.
//
// argmin_k ||p-c||^2 == argmax_k (p.c - 0.5*||c||^2). Inner loop: 3 FFMA + cmp/sel.
// Strict '>' with ascending k keeps the LOWEST index on ties (matches argmin).

#define CR_HW 262144  // 512*512, used for fast path shifts

__global__ void __launch_bounds__(256)
color_reduce_kernel(const float* __restrict__ x,
                    const float* __restrict__ pal,
                    float* __restrict__ out,
                    int npix, int hw, int ncol)
{
    __shared__ float4 spal[64];

    int t = threadIdx.x;
    if (t < ncol && t < 64) {
        float cx = pal[t * 3 + 0];
        float cy = pal[t * 3 + 1];
        float cz = pal[t * 3 + 2];
        float h  = -0.5f * (cx * cx + cy * cy + cz * cz);
        spal[t] = make_float4(cx, cy, cz, h);
    }
    __syncthreads();

    int gid = blockIdx.x * blockDim.x + t;
    int i0  = gid * 4;
    if (i0 >= npix) return;

    // batch / plane-offset split. hw is a power of two in practice but keep generic.
    int b, q;
    if (hw == CR_HW) {
        b = i0 >> 18;
        q = i0 & (CR_HW - 1);
    } else {
        b = i0 / hw;
        q = i0 - b * hw;
    }

    const float* base = x + (size_t)b * 3 * (size_t)hw + q;
    float*      obase = out + (size_t)b * 3 * (size_t)hw + q;

    if (i0 + 3 < npix) {
        // vector path: 4 pixels, float4 per plane
        float4 pr = *reinterpret_cast<const float4*>(base);
        float4 pg = *reinterpret_cast<const float4*>(base + hw);
        float4 pb = *reinterpret_cast<const float4*>(base + 2 * hw);

        float rr[4] = {pr.x, pr.y, pr.z, pr.w};
        float gg[4] = {pg.x, pg.y, pg.z, pg.w};
        float bb[4] = {pb.x, pb.y, pb.z, pb.w};

        float best[4];
        int   bid[4];
#pragma unroll
        for (int p = 0; p < 4; p++) { best[p] = -3.0e38f; bid[p] = 0; }

        if (ncol == 64) {
#pragma unroll 16
            for (int k = 0; k < 64; k++) {
                float4 c = spal[k];
#pragma unroll
                for (int p = 0; p < 4; p++) {
                    float s = fmaf(rr[p], c.x,
                               fmaf(gg[p], c.y,
                                fmaf(bb[p], c.z, c.w)));
                    if (s > best[p]) { best[p] = s; bid[p] = k; }
                }
            }
        } else {
            for (int k = 0; k < ncol; k++) {
                float4 c = spal[k];
#pragma unroll
                for (int p = 0; p < 4; p++) {
                    float s = fmaf(rr[p], c.x,
                               fmaf(gg[p], c.y,
                                fmaf(bb[p], c.z, c.w)));
                    if (s > best[p]) { best[p] = s; bid[p] = k; }
                }
            }
        }

        float4 c0 = spal[bid[0]];
        float4 c1 = spal[bid[1]];
        float4 c2 = spal[bid[2]];
        float4 c3 = spal[bid[3]];

        *reinterpret_cast<float4*>(obase)          = make_float4(c0.x, c1.x, c2.x, c3.x);
        *reinterpret_cast<float4*>(obase + hw)     = make_float4(c0.y, c1.y, c2.y, c3.y);
        *reinterpret_cast<float4*>(obase + 2 * hw) = make_float4(c0.z, c1.z, c2.z, c3.z);
    } else {
        // scalar tail (only hit if npix % 4 != 0)
        for (int i = i0; i < npix; i++) {
            int bb2, qq;
            if (hw == CR_HW) { bb2 = i >> 18; qq = i & (CR_HW - 1); }
            else             { bb2 = i / hw;  qq = i - bb2 * hw; }
            const float* pbase = x + (size_t)bb2 * 3 * (size_t)hw + qq;
            float px = pbase[0], py = pbase[hw], pz = pbase[2 * hw];
            float bestv = -3.0e38f; int bk = 0;
            for (int k = 0; k < ncol; k++) {
                float4 c = spal[k];
                float s = fmaf(px, c.x, fmaf(py, c.y, fmaf(pz, c.z, c.w)));
                if (s > bestv) { bestv = s; bk = k; }
            }
            float4 c = spal[bk];
            float* ob = out + (size_t)bb2 * 3 * (size_t)hw + qq;
            ob[0] = c.x; ob[hw] = c.y; ob[2 * hw] = c.z;
        }
    }
}

extern "C" void kernel_launch(void* const* d_in, const int* in_sizes, int n_in,
                              void* d_out, int out_size)
{
    const float* x   = (const float*)d_in[0];
    const float* pal = (const float*)d_in[1];
    float*       out = (float*)d_out;

    int nelem = in_sizes[0];          // B*3*H*W
    int ncol  = in_sizes[1] / 3;      // 64
    int hw    = CR_HW;                // 512*512 per problem shape
    // If total doesn't match B*3*HW assumption, fall back to treating the
    // whole thing as one batch of (nelem/3) pixels per plane.
    if (nelem % (3 * hw) != 0) {
        hw = nelem / 3;
    }
    int npix = nelem / 3;

    int threads = 256;
    int groups  = (npix + 3) / 4;
    int blocks  = (groups + threads - 1) / threads;

    color_reduce_kernel<<<blocks, threads>>>(x, pal, out, npix, hw, ncol);
}

// round 2
// speedup vs baseline: 1.0234x; 1.0234x over previous
#include <cuda_runtime.h>
#include <cuda_bf16.h>
#include <cfloat>

// ColorReducer: out[b,:,h,w] = palette[argmin_k ||x[b,:,h,w] - palette[k]||^2]
// argmin_k ||p-c||^2 == argmax_k s_k, s_k = p.c - 0.5*||c||^2.
//
// Strategy (issue-bound kernel):
//  - fma.rn.f32x2 packed FMA: 2 pixels per FFMA2 instruction (bit-identical to FFMA.rn)
//  - tournament argmax: FMNMX-reduce groups of 4 colors, track only group winner,
//    recompute winning group's 4 scores at the end (identical FMA order => exact
//    equality match; descending-priority select keeps first index => argmin tie rule).

#define CR_HW 262144

#define F2FMA(d, a, b, c) \
    asm("fma.rn.f32x2 %0, %1, %2, %3;" : "=l"(d) : "l"(a), "l"(b), "l"(c))
#define F2PACK(d, lo, hi) \
    asm("mov.b64 %0, {%1, %2};" : "=l"(d) : "f"(lo), "f"(hi))
#define F2UNPACK(lo, hi, v) \
    asm("mov.b64 {%0, %1}, %2;" : "=f"(lo), "=f"(hi) : "l"(v))

typedef unsigned long long ull;

__global__ void __launch_bounds__(256)
color_reduce_f2_kernel(const float* __restrict__ x,
                       const float* __restrict__ pal,
                       float* __restrict__ out,
                       int npix)
{
    // duplicated palette for packed math: [k] = cx,cx,cy,cy,cz,cz,h,h
    __shared__ __align__(16) float spal2f[64][8];
    // compact palette for finale / gather: [k] = {cx,cy,cz,h}
    __shared__ float4 spalc[64];

    int t = threadIdx.x;
    if (t < 64) {
        float cx = pal[t * 3 + 0];
        float cy = pal[t * 3 + 1];
        float cz = pal[t * 3 + 2];
        float h  = -0.5f * (cx * cx + cy * cy + cz * cz);
        spal2f[t][0] = cx; spal2f[t][1] = cx;
        spal2f[t][2] = cy; spal2f[t][3] = cy;
        spal2f[t][4] = cz; spal2f[t][5] = cz;
        spal2f[t][6] = h;  spal2f[t][7] = h;
        spalc[t] = make_float4(cx, cy, cz, h);
    }
    __syncthreads();

    int gid = blockIdx.x * blockDim.x + t;
    int i0  = gid * 4;
    if (i0 >= npix) return;

    int b = i0 >> 18;             // / CR_HW
    int q = i0 & (CR_HW - 1);

    const float* base  = x   + (size_t)b * 3 * CR_HW + q;
    float*       obase = out + (size_t)b * 3 * CR_HW + q;

    if (i0 + 3 < npix) {
        float4 pr = *reinterpret_cast<const float4*>(base);
        float4 pg = *reinterpret_cast<const float4*>(base + CR_HW);
        float4 pb = *reinterpret_cast<const float4*>(base + 2 * CR_HW);

        float rr[4] = {pr.x, pr.y, pr.z, pr.w};
        float gg[4] = {pg.x, pg.y, pg.z, pg.w};
        float bb[4] = {pb.x, pb.y, pb.z, pb.w};

        // packed pixel pairs: [pair] for each channel
        ull r01, r23, g01, g23, b01, b23;
        F2PACK(r01, rr[0], rr[1]); F2PACK(r23, rr[2], rr[3]);
        F2PACK(g01, gg[0], gg[1]); F2PACK(g23, gg[2], gg[3]);
        F2PACK(b01, bb[0], bb[1]); F2PACK(b23, bb[2], bb[3]);

        float best[4];
        int   bgrp[4];
#pragma unroll
        for (int p = 0; p < 4; p++) { best[p] = -FLT_MAX; bgrp[p] = 0; }

#pragma unroll
        for (int g = 0; g < 16; g++) {
            float sf[4][4];   // [color][pixel]
#pragma unroll
            for (int c = 0; c < 4; c++) {
                int k = g * 4 + c;
                const ulonglong2* pp = reinterpret_cast<const ulonglong2*>(spal2f[k]);
                ulonglong2 v0 = pp[0];   // {cx,cx},{cy,cy}
                ulonglong2 v1 = pp[1];   // {cz,cz},{h,h}
                ull cxx = v0.x, cyy = v0.y, czz = v1.x, hh = v1.y;

                ull sA, sB;
                F2FMA(sA, b01, czz, hh);
                F2FMA(sA, g01, cyy, sA);
                F2FMA(sA, r01, cxx, sA);
                F2FMA(sB, b23, czz, hh);
                F2FMA(sB, g23, cyy, sB);
                F2FMA(sB, r23, cxx, sB);
                F2UNPACK(sf[c][0], sf[c][1], sA);
                F2UNPACK(sf[c][2], sf[c][3], sB);
            }
#pragma unroll
            for (int p = 0; p < 4; p++) {
                float m = fmaxf(fmaxf(sf[0][p], sf[1][p]),
                                fmaxf(sf[2][p], sf[3][p]));
                if (m > best[p]) { best[p] = m; bgrp[p] = g; }
            }
        }

        // finale: recompute winning group's 4 scores (bit-identical FMA order),
        // pick first index that equals the max, gather its color.
        float4 cc[4];
#pragma unroll
        for (int p = 0; p < 4; p++) {
            int k0 = bgrp[p] * 4;
            float4 c0 = spalc[k0 + 0];
            float4 c1 = spalc[k0 + 1];
            float4 c2 = spalc[k0 + 2];
            float4 c3 = spalc[k0 + 3];
            float px = rr[p], py = gg[p], pz = bb[p];
            float s0 = fmaf(px, c0.x, fmaf(py, c0.y, fmaf(pz, c0.z, c0.w)));
            float s1 = fmaf(px, c1.x, fmaf(py, c1.y, fmaf(pz, c1.z, c1.w)));
            float s2 = fmaf(px, c2.x, fmaf(py, c2.y, fmaf(pz, c2.z, c2.w)));
            float s3 = fmaf(px, c3.x, fmaf(py, c3.y, fmaf(pz, c3.z, c3.w)));
            int j = 3;
            if (s2 == best[p]) j = 2;
            if (s1 == best[p]) j = 1;
            if (s0 == best[p]) j = 0;
            cc[p] = spalc[k0 + j];
        }

        *reinterpret_cast<float4*>(obase) =
            make_float4(cc[0].x, cc[1].x, cc[2].x, cc[3].x);
        *reinterpret_cast<float4*>(obase + CR_HW) =
            make_float4(cc[0].y, cc[1].y, cc[2].y, cc[3].y);
        *reinterpret_cast<float4*>(obase + 2 * CR_HW) =
            make_float4(cc[0].z, cc[1].z, cc[2].z, cc[3].z);
    } else {
        // scalar tail (not hit for 512x512x8 shapes)
        for (int i = i0; i < npix; i++) {
            int b2 = i >> 18;
            int q2 = i & (CR_HW - 1);
            const float* pb2 = x + (size_t)b2 * 3 * CR_HW + q2;
            float px = pb2[0], py = pb2[CR_HW], pz = pb2[2 * CR_HW];
            float bestv = -FLT_MAX; int bk = 0;
            for (int k = 0; k < 64; k++) {
                float4 c = spalc[k];
                float s = fmaf(px, c.x, fmaf(py, c.y, fmaf(pz, c.z, c.w)));
                if (s > bestv) { bestv = s; bk = k; }
            }
            float4 c = spalc[bk];
            float* ob = out + (size_t)b2 * 3 * CR_HW + q2;
            ob[0] = c.x; ob[CR_HW] = c.y; ob[2 * CR_HW] = c.z;
        }
    }
}

// generic fallback (any shape / ncol) — simple, correct, only used off the fast path
__global__ void color_reduce_generic_kernel(const float* __restrict__ x,
                                            const float* __restrict__ pal,
                                            float* __restrict__ out,
                                            int npix, int hw, int ncol)
{
    extern __shared__ float4 gpal[];
    int t = threadIdx.x;
    for (int k = t; k < ncol; k += blockDim.x) {
        float cx = pal[k * 3 + 0], cy = pal[k * 3 + 1], cz = pal[k * 3 + 2];
        gpal[k] = make_float4(cx, cy, cz, -0.5f * (cx * cx + cy * cy + cz * cz));
    }
    __syncthreads();
    int i = blockIdx.x * blockDim.x + t;
    if (i >= npix) return;
    int b = i / hw, q = i - b * hw;
    const float* pb = x + (size_t)b * 3 * (size_t)hw + q;
    float px = pb[0], py = pb[hw], pz = pb[2 * hw];
    float bestv = -FLT_MAX; int bk = 0;
    for (int k = 0; k < ncol; k++) {
        float4 c = gpal[k];
        float s = fmaf(px, c.x, fmaf(py, c.y, fmaf(pz, c.z, c.w)));
        if (s > bestv) { bestv = s; bk = k; }
    }
    float4 c = gpal[bk];
    float* ob = out + (size_t)b * 3 * (size_t)hw + q;
    ob[0] = c.x; ob[hw] = c.y; ob[2 * hw] = c.z;
}

extern "C" void kernel_launch(void* const* d_in, const int* in_sizes, int n_in,
                              void* d_out, int out_size)
{
    const float* x   = (const float*)d_in[0];
    const float* pal = (const float*)d_in[1];
    float*       out = (float*)d_out;

    int nelem = in_sizes[0];
    int ncol  = in_sizes[1] / 3;
    int npix  = nelem / 3;

    if (ncol == 64 && nelem % (3 * CR_HW) == 0) {
        int threads = 256;
        int groups  = (npix + 3) / 4;
        int blocks  = (groups + threads - 1) / threads;
        color_reduce_f2_kernel<<<blocks, threads>>>(x, pal, out, npix);
    } else {
        int hw = npix;  // treat as single batch
        if (nelem % (3 * CR_HW) == 0) hw = CR_HW;
        int threads = 256;
        int blocks  = (npix + threads - 1) / threads;
        color_reduce_generic_kernel<<<blocks, threads, ncol * sizeof(float4)>>>(
            x, pal, out, npix, hw, ncol);
    }
}